// round 8
// baseline (speedup 1.0000x reference)
#include <cuda_runtime.h>

#define Bb 96
#define Tt 48
#define LD 64
#define GD 64
#define MT 10
#define HH 128

#define NT 512
#define SW_F 16384
#define SH1_STRIDE 129
#define SH1_F (Bb*SH1_STRIDE)
#define LOC_CTAS 576
#define GLB_CTAS 12

typedef unsigned long long ull;

__device__ float g_A[Bb*Tt*HH];   // locals @ lw1[:64]          [4608,128]
__device__ float g_Bg[Bb*HH];     // globals @ lw1[64:] + lb1   [96,128]
__device__ float g_P[Bb*HH];      // sampled-locals @ gw1[:640] [96,128]
__device__ float g_Q[Bb*HH];      // globals @ gw1[640:] + gb1  [96,128]

__device__ __forceinline__ ull pack2(float lo, float hi){
    ull r; asm("mov.b64 %0, {%1, %2};" : "=l"(r) : "f"(lo), "f"(hi)); return r;
}
__device__ __forceinline__ void fma2(ull &d, ull a, ull b){
    asm("fma.rn.f32x2 %0, %1, %2, %0;" : "+l"(d) : "l"(a), "l"(b));
}
__device__ __forceinline__ float2 unpack2(ull v){
    float2 f; asm("mov.b64 {%0, %1}, %2;" : "=f"(f.x), "=f"(f.y) : "l"(v)); return f;
}

// ---------------------------------------------------------------------------
// Precompute part A: A[i*48+t][h] = locals[i,t,:] @ lw1[0:64,h]
// grid (96, 4): 12 t-rows per CTA; acc[12] -> no spill.
// ---------------------------------------------------------------------------
__global__ __launch_bounds__(128) void precompute_a_kernel(
    const float* __restrict__ locals_, const float* __restrict__ lw1)
{
    __shared__ float ltile[12*LD];

    const int i   = blockIdx.x;
    const int t0  = blockIdx.y * 12;
    const int tid = threadIdx.x;

    for (int idx = tid; idx < 12*LD; idx += 128)
        ltile[idx] = locals_[(i*Tt + t0)*LD + idx];
    __syncthreads();

    const int h = tid;

    float acc[12];
    #pragma unroll
    for (int t = 0; t < 12; t++) acc[t] = 0.f;
    for (int k = 0; k < LD; k++) {
        float w = lw1[k*HH + h];
        #pragma unroll
        for (int t = 0; t < 12; t++) acc[t] += ltile[t*LD + k] * w;
    }
    #pragma unroll
    for (int t = 0; t < 12; t++) g_A[(i*Tt + t0 + t)*HH + h] = acc[t];
}

// ---------------------------------------------------------------------------
// Precompute part B: Bg, Q, P per batch-row i.
// ---------------------------------------------------------------------------
__global__ __launch_bounds__(128) void precompute_pqb_kernel(
    const float* __restrict__ globals_, const float* __restrict__ locals_,
    const float* __restrict__ gw1, const float* __restrict__ gb1,
    const float* __restrict__ lw1, const float* __restrict__ lb1,
    const int* __restrict__ idx_t)
{
    __shared__ float lsrow[MT*LD];
    __shared__ float grow[GD];
    __shared__ int   sidx[MT];

    const int i = blockIdx.x;
    const int tid = threadIdx.x;

    if (tid < GD) grow[tid] = globals_[i*GD + tid];
    if (tid < MT) sidx[tid] = idx_t[i*MT + tid];
    __syncthreads();
    for (int idx = tid; idx < MT*LD; idx += 128) {
        int m = idx >> 6, k = idx & 63;
        lsrow[idx] = locals_[(i*Tt + sidx[m])*LD + k];
    }
    __syncthreads();

    const int h = tid;

    float bv = lb1[h];
    for (int k = 0; k < GD; k++) bv += grow[k] * lw1[(LD + k)*HH + h];
    g_Bg[i*HH + h] = bv;

    float qv = gb1[h];
    for (int k = 0; k < GD; k++) qv += grow[k] * gw1[(MT*LD + k)*HH + h];
    g_Q[i*HH + h] = qv;

    float pv = 0.f;
    for (int k = 0; k < MT*LD; k++) pv += lsrow[k] * gw1[k*HH + h];
    g_P[i*HH + h] = pv;
}

// ---------------------------------------------------------------------------
// Unified MI kernel: CTAs [0,576) = locals path, [576,588) = globals path.
// 512 threads: 2 j-groups (48 j each) x 16 jg x 16 hg; 3 j per thread.
// Per row: h1 = relu(arow + brows[j]); h2 = relu(h1@w2 + b2); out = h2.w3 + b3
// ---------------------------------------------------------------------------
__global__ void __launch_bounds__(NT, 1) mi_kernel(
    const float* __restrict__ lw2, const float* __restrict__ lb2,
    const float* __restrict__ lw3, const float* __restrict__ lb3,
    const float* __restrict__ gw2, const float* __restrict__ gb2,
    const float* __restrict__ gw3, const float* __restrict__ gb3,
    float* __restrict__ out_l, float* __restrict__ out_g)
{
    extern __shared__ float sm[];
    float* sw    = sm;                 // [128][128] w2, 64 KB
    float* sh1   = sm + SW_F;          // [96][129]  h1 tile
    float* sarow = sh1 + SH1_F;        // [128]
    float* sw3   = sarow + HH;         // [128]

    const int bid = blockIdx.x;
    const bool isg = (bid >= LOC_CTAS);

    const float* w2 = isg ? gw2 : lw2;
    const float* b2 = isg ? gb2 : lb2;
    const float* w3 = isg ? gw3 : lw3;
    const float* b3 = isg ? gb3 : lb3;
    const float* arows = isg ? g_P : g_A;
    const float* brows = isg ? g_Q : g_Bg;
    float* out = isg ? out_g : out_l;
    const int row0 = (isg ? (bid - LOC_CTAS) : bid) * 8;

    const int tid = threadIdx.x;
    const int grp = tid >> 8;          // 0/1: j-half
    const int t   = tid & 255;
    const int jg  = t >> 4;            // 0..15
    const int hg  = t & 15;            // 0..15
    const int hA  = hg * 4;
    const int hB  = 64 + hg * 4;
    const int jb  = grp*48 + jg*3;

    // Load w2, w3 into smem
    const float4* w24 = (const float4*)w2;
    float4* sw4 = (float4*)sw;
    for (int idx = tid; idx < SW_F/4; idx += NT) sw4[idx] = w24[idx];
    if (tid < HH) sw3[tid] = w3[tid];

    // b2 accumulator init (pairs), b3
    float2 q0 = *(const float2*)(b2 + hA);
    float2 q1 = *(const float2*)(b2 + hA + 2);
    float2 q2 = *(const float2*)(b2 + hB);
    float2 q3 = *(const float2*)(b2 + hB + 2);
    ull binit[4] = { pack2(q0.x,q0.y), pack2(q1.x,q1.y), pack2(q2.x,q2.y), pack2(q3.x,q3.y) };
    const float b3v = b3[0];

    const ull* swp = (const ull*)sw;   // w2 pairs: swp[k*64 + h/2]

    for (int r = 0; r < 8; r++) {
        const int row = row0 + r;

        __syncthreads();   // prior iter done reading sh1/sarow; first iter: orders sw loads
        if (tid < HH) sarow[tid] = arows[row*HH + tid];
        __syncthreads();

        // h1[j][k] = relu(arow[k] + brows[j][k])
        for (int idx = tid; idx < Bb*HH; idx += NT) {
            int k = idx & 127;
            float v = sarow[k] + brows[idx];
            sh1[(idx >> 7)*SH1_STRIDE + k] = v > 0.f ? v : 0.f;
        }
        __syncthreads();

        ull acc[3][4];
        #pragma unroll
        for (int jj = 0; jj < 3; jj++) {
            #pragma unroll
            for (int p = 0; p < 4; p++) acc[jj][p] = binit[p];
        }

        #pragma unroll 4
        for (int k = 0; k < HH; k++) {
            ull bf0 = swp[(k << 6) + hg*2];
            ull bf1 = swp[(k << 6) + hg*2 + 1];
            ull bf2 = swp[(k << 6) + 32 + hg*2];
            ull bf3 = swp[(k << 6) + 32 + hg*2 + 1];
            #pragma unroll
            for (int jj = 0; jj < 3; jj++) {
                float a = sh1[(jb + jj)*SH1_STRIDE + k];
                ull a2 = pack2(a, a);
                fma2(acc[jj][0], a2, bf0);
                fma2(acc[jj][1], a2, bf1);
                fma2(acc[jj][2], a2, bf2);
                fma2(acc[jj][3], a2, bf3);
            }
        }

        // Epilogue: relu(h2) . w3, reduce over 16 hg lanes
        #pragma unroll
        for (int jj = 0; jj < 3; jj++) {
            float2 v0 = unpack2(acc[jj][0]);
            float2 v1 = unpack2(acc[jj][1]);
            float2 v2 = unpack2(acc[jj][2]);
            float2 v3 = unpack2(acc[jj][3]);
            float s = fmaxf(v0.x,0.f)*sw3[hA]   + fmaxf(v0.y,0.f)*sw3[hA+1]
                    + fmaxf(v1.x,0.f)*sw3[hA+2] + fmaxf(v1.y,0.f)*sw3[hA+3]
                    + fmaxf(v2.x,0.f)*sw3[hB]   + fmaxf(v2.y,0.f)*sw3[hB+1]
                    + fmaxf(v3.x,0.f)*sw3[hB+2] + fmaxf(v3.y,0.f)*sw3[hB+3];
            s += __shfl_xor_sync(0xffffffffu, s, 1);
            s += __shfl_xor_sync(0xffffffffu, s, 2);
            s += __shfl_xor_sync(0xffffffffu, s, 4);
            s += __shfl_xor_sync(0xffffffffu, s, 8);
            if (hg == 0) {
                int j = jb + jj;
                int o;
                if (!isg) {
                    int ii = row / Tt, tt = row - ii*Tt;
                    o = tt*(Bb*Bb) + ii*Bb + j;      // locals_mi[t][i][j]
                } else {
                    o = row*Bb + j;                   // globals_mi[i][j]
                }
                out[o] = s + b3v;
            }
        }
    }
}

// ---------------------------------------------------------------------------
extern "C" void kernel_launch(void* const* d_in, const int* in_sizes, int n_in,
                              void* d_out, int out_size)
{
    const float* globals_ = (const float*)d_in[0];
    const float* locals_  = (const float*)d_in[1];
    const float* gw1 = (const float*)d_in[2];
    const float* gb1 = (const float*)d_in[3];
    const float* gw2 = (const float*)d_in[4];
    const float* gb2 = (const float*)d_in[5];
    const float* gw3 = (const float*)d_in[6];
    const float* gb3 = (const float*)d_in[7];
    const float* lw1 = (const float*)d_in[8];
    const float* lb1 = (const float*)d_in[9];
    const float* lw2 = (const float*)d_in[10];
    const float* lb2 = (const float*)d_in[11];
    const float* lw3 = (const float*)d_in[12];
    const float* lb3 = (const float*)d_in[13];
    const int*  idx_t = (const int*)d_in[14];

    float* out = (float*)d_out;

    // Pass-through outputs
    cudaMemcpyAsync(out, globals_, (size_t)Bb*GD*sizeof(float),
                    cudaMemcpyDeviceToDevice, 0);
    cudaMemcpyAsync(out + Bb*GD, locals_, (size_t)Bb*Tt*LD*sizeof(float),
                    cudaMemcpyDeviceToDevice, 0);

    precompute_a_kernel<<<dim3(Bb, 4), 128>>>(locals_, lw1);
    precompute_pqb_kernel<<<Bb, 128>>>(globals_, locals_, gw1, gb1, lw1, lb1, idx_t);

    size_t smem = (size_t)(SW_F + SH1_F + HH + HH) * sizeof(float);
    cudaFuncSetAttribute(mi_kernel, cudaFuncAttributeMaxDynamicSharedMemorySize, (int)smem);

    float* gmi = out + (Bb*GD + Bb*Tt*LD);
    float* lmi = gmi + Bb*Bb;

    mi_kernel<<<LOC_CTAS + GLB_CTAS, NT, smem>>>(lw2, lb2, lw3, lb3,
                                                 gw2, gb2, gw3, gb3,
                                                 lmi, gmi);
}

// round 9
// speedup vs baseline: 1.1306x; 1.1306x over previous
#include <cuda_runtime.h>

#define Bb 96
#define Tt 48
#define LD 64
#define GD 64
#define MT 10
#define HH 128

#define NT 256
#define SW_F 16384
#define SH1_STRIDE 129
#define SH1_F (Bb*SH1_STRIDE)
#define LOC_CTAS 576
#define GLB_CTAS 12

typedef unsigned long long ull;

__device__ float g_A[Bb*Tt*HH];   // locals @ lw1[:64]          [4608,128]
__device__ float g_Bg[Bb*HH];     // globals @ lw1[64:] + lb1   [96,128]
__device__ float g_P[Bb*HH];      // sampled-locals @ gw1[:640] [96,128]
__device__ float g_Q[Bb*HH];      // globals @ gw1[640:] + gb1  [96,128]

__device__ __forceinline__ ull pack2(float lo, float hi){
    ull r; asm("mov.b64 %0, {%1, %2};" : "=l"(r) : "f"(lo), "f"(hi)); return r;
}
__device__ __forceinline__ void fma2(ull &d, ull a, ull b){
    asm("fma.rn.f32x2 %0, %1, %2, %0;" : "+l"(d) : "l"(a), "l"(b));
}
__device__ __forceinline__ float2 unpack2(ull v){
    float2 f; asm("mov.b64 {%0, %1}, %2;" : "=f"(f.x), "=f"(f.y) : "l"(v)); return f;
}

// ---------------------------------------------------------------------------
// Precompute part A: A[i*48+t][h] = locals[i,t,:] @ lw1[0:64,h]
// grid (96, 8): 6 t-rows per CTA; acc[6]; 768 CTAs for latency hiding.
// ---------------------------------------------------------------------------
__global__ __launch_bounds__(128) void precompute_a_kernel(
    const float* __restrict__ locals_, const float* __restrict__ lw1)
{
    __shared__ float ltile[6*LD];

    const int i   = blockIdx.x;
    const int t0  = blockIdx.y * 6;
    const int tid = threadIdx.x;

    for (int idx = tid; idx < 6*LD; idx += 128)
        ltile[idx] = locals_[(i*Tt + t0)*LD + idx];
    __syncthreads();

    const int h = tid;

    float acc[6];
    #pragma unroll
    for (int t = 0; t < 6; t++) acc[t] = 0.f;
    #pragma unroll 8
    for (int k = 0; k < LD; k++) {
        float w = lw1[k*HH + h];
        #pragma unroll
        for (int t = 0; t < 6; t++) acc[t] += ltile[t*LD + k] * w;
    }
    #pragma unroll
    for (int t = 0; t < 6; t++) g_A[(i*Tt + t0 + t)*HH + h] = acc[t];
}

// ---------------------------------------------------------------------------
// Precompute part B: Bg, Q, P per batch-row i.
// ---------------------------------------------------------------------------
__global__ __launch_bounds__(128) void precompute_pqb_kernel(
    const float* __restrict__ globals_, const float* __restrict__ locals_,
    const float* __restrict__ gw1, const float* __restrict__ gb1,
    const float* __restrict__ lw1, const float* __restrict__ lb1,
    const int* __restrict__ idx_t)
{
    __shared__ float lsrow[MT*LD];
    __shared__ float grow[GD];
    __shared__ int   sidx[MT];

    const int i = blockIdx.x;
    const int tid = threadIdx.x;

    if (tid < GD) grow[tid] = globals_[i*GD + tid];
    if (tid < MT) sidx[tid] = idx_t[i*MT + tid];
    __syncthreads();
    for (int idx = tid; idx < MT*LD; idx += 128) {
        int m = idx >> 6, k = idx & 63;
        lsrow[idx] = locals_[(i*Tt + sidx[m])*LD + k];
    }
    __syncthreads();

    const int h = tid;

    float bv = lb1[h];
    for (int k = 0; k < GD; k++) bv += grow[k] * lw1[(LD + k)*HH + h];
    g_Bg[i*HH + h] = bv;

    float qv = gb1[h];
    for (int k = 0; k < GD; k++) qv += grow[k] * gw1[(MT*LD + k)*HH + h];
    g_Q[i*HH + h] = qv;

    float pv = 0.f;
    for (int k = 0; k < MT*LD; k++) pv += lsrow[k] * gw1[k*HH + h];
    g_P[i*HH + h] = pv;
}

// ---------------------------------------------------------------------------
// Unified MI kernel: CTAs [0,576) = locals path, [576,588) = globals path.
// R1-proven geometry: 256 threads, 16 j-groups (6 j) x 16 h-groups (8 h).
// Per row: h1 = relu(arow + brows[j]); h2 = relu(h1@w2 + b2); out = h2.w3 + b3
// ---------------------------------------------------------------------------
__global__ void __launch_bounds__(NT, 1) mi_kernel(
    const float* __restrict__ lw2, const float* __restrict__ lb2,
    const float* __restrict__ lw3, const float* __restrict__ lb3,
    const float* __restrict__ gw2, const float* __restrict__ gb2,
    const float* __restrict__ gw3, const float* __restrict__ gb3,
    float* __restrict__ out_l, float* __restrict__ out_g)
{
    extern __shared__ float sm[];
    float* sw    = sm;                 // [128][128] w2, 64 KB
    float* sh1   = sm + SW_F;          // [96][129]  h1 tile
    float* sarow = sh1 + SH1_F;        // [128]
    float* sw3   = sarow + HH;         // [128]

    const int bid = blockIdx.x;
    const bool isg = (bid >= LOC_CTAS);

    const float* w2 = isg ? gw2 : lw2;
    const float* b2 = isg ? gb2 : lb2;
    const float* w3 = isg ? gw3 : lw3;
    const float* b3 = isg ? gb3 : lb3;
    const float* arows = isg ? g_P : g_A;
    const float* brows = isg ? g_Q : g_Bg;
    float* out = isg ? out_g : out_l;
    const int row0 = (isg ? (bid - LOC_CTAS) : bid) * 8;

    const int tid = threadIdx.x;
    const int jg = tid >> 4;           // 0..15  (2 per warp)
    const int hg = tid & 15;           // 0..15
    const int hA = hg * 4;
    const int hB = 64 + hg * 4;
    const int jb = jg * 6;

    // Load w2, w3 into smem
    const float4* w24 = (const float4*)w2;
    float4* sw4 = (float4*)sw;
    for (int idx = tid; idx < SW_F/4; idx += NT) sw4[idx] = w24[idx];
    if (tid < HH) sw3[tid] = w3[tid];

    // b2 accumulator init (pairs), b3
    float2 q0 = *(const float2*)(b2 + hA);
    float2 q1 = *(const float2*)(b2 + hA + 2);
    float2 q2 = *(const float2*)(b2 + hB);
    float2 q3 = *(const float2*)(b2 + hB + 2);
    ull binit[4] = { pack2(q0.x,q0.y), pack2(q1.x,q1.y), pack2(q2.x,q2.y), pack2(q3.x,q3.y) };
    const float b3v = b3[0];

    const ull* swp = (const ull*)sw;   // w2 pairs: swp[k*64 + h/2]

    for (int r = 0; r < 8; r++) {
        const int row = row0 + r;

        __syncthreads();   // prior iter done reading sh1/sarow; first iter: orders sw loads
        if (tid < HH) sarow[tid] = arows[row*HH + tid];
        __syncthreads();

        // h1[j][k] = relu(arow[k] + brows[j][k])
        for (int idx = tid; idx < Bb*HH; idx += NT) {
            int k = idx & 127;
            float v = sarow[k] + brows[idx];
            sh1[(idx >> 7)*SH1_STRIDE + k] = v > 0.f ? v : 0.f;
        }
        __syncthreads();

        ull acc[6][4];
        #pragma unroll
        for (int jj = 0; jj < 6; jj++) {
            #pragma unroll
            for (int p = 0; p < 4; p++) acc[jj][p] = binit[p];
        }

        #pragma unroll 4
        for (int k = 0; k < HH; k++) {
            ull bf0 = swp[(k << 6) + hg*2];
            ull bf1 = swp[(k << 6) + hg*2 + 1];
            ull bf2 = swp[(k << 6) + 32 + hg*2];
            ull bf3 = swp[(k << 6) + 32 + hg*2 + 1];
            #pragma unroll
            for (int jj = 0; jj < 6; jj++) {
                float a = sh1[(jb + jj)*SH1_STRIDE + k];
                ull a2 = pack2(a, a);
                fma2(acc[jj][0], a2, bf0);
                fma2(acc[jj][1], a2, bf1);
                fma2(acc[jj][2], a2, bf2);
                fma2(acc[jj][3], a2, bf3);
            }
        }

        // Epilogue: relu(h2) . w3, reduce over 16 hg lanes
        #pragma unroll
        for (int jj = 0; jj < 6; jj++) {
            float2 v0 = unpack2(acc[jj][0]);
            float2 v1 = unpack2(acc[jj][1]);
            float2 v2 = unpack2(acc[jj][2]);
            float2 v3 = unpack2(acc[jj][3]);
            float s = fmaxf(v0.x,0.f)*sw3[hA]   + fmaxf(v0.y,0.f)*sw3[hA+1]
                    + fmaxf(v1.x,0.f)*sw3[hA+2] + fmaxf(v1.y,0.f)*sw3[hA+3]
                    + fmaxf(v2.x,0.f)*sw3[hB]   + fmaxf(v2.y,0.f)*sw3[hB+1]
                    + fmaxf(v3.x,0.f)*sw3[hB+2] + fmaxf(v3.y,0.f)*sw3[hB+3];
            s += __shfl_xor_sync(0xffffffffu, s, 1);
            s += __shfl_xor_sync(0xffffffffu, s, 2);
            s += __shfl_xor_sync(0xffffffffu, s, 4);
            s += __shfl_xor_sync(0xffffffffu, s, 8);
            if (hg == 0) {
                int j = jb + jj;
                int o;
                if (!isg) {
                    int ii = row / Tt, tt = row - ii*Tt;
                    o = tt*(Bb*Bb) + ii*Bb + j;      // locals_mi[t][i][j]
                } else {
                    o = row*Bb + j;                   // globals_mi[i][j]
                }
                out[o] = s + b3v;
            }
        }
    }
}

// ---------------------------------------------------------------------------
extern "C" void kernel_launch(void* const* d_in, const int* in_sizes, int n_in,
                              void* d_out, int out_size)
{
    const float* globals_ = (const float*)d_in[0];
    const float* locals_  = (const float*)d_in[1];
    const float* gw1 = (const float*)d_in[2];
    const float* gb1 = (const float*)d_in[3];
    const float* gw2 = (const float*)d_in[4];
    const float* gb2 = (const float*)d_in[5];
    const float* gw3 = (const float*)d_in[6];
    const float* gb3 = (const float*)d_in[7];
    const float* lw1 = (const float*)d_in[8];
    const float* lb1 = (const float*)d_in[9];
    const float* lw2 = (const float*)d_in[10];
    const float* lb2 = (const float*)d_in[11];
    const float* lw3 = (const float*)d_in[12];
    const float* lb3 = (const float*)d_in[13];
    const int*  idx_t = (const int*)d_in[14];

    float* out = (float*)d_out;

    // Pass-through outputs
    cudaMemcpyAsync(out, globals_, (size_t)Bb*GD*sizeof(float),
                    cudaMemcpyDeviceToDevice, 0);
    cudaMemcpyAsync(out + Bb*GD, locals_, (size_t)Bb*Tt*LD*sizeof(float),
                    cudaMemcpyDeviceToDevice, 0);

    precompute_a_kernel<<<dim3(Bb, 8), 128>>>(locals_, lw1);
    precompute_pqb_kernel<<<Bb, 128>>>(globals_, locals_, gw1, gb1, lw1, lb1, idx_t);

    size_t smem = (size_t)(SW_F + SH1_F + HH + HH) * sizeof(float);
    cudaFuncSetAttribute(mi_kernel, cudaFuncAttributeMaxDynamicSharedMemorySize, (int)smem);

    float* gmi = out + (Bb*GD + Bb*Tt*LD);
    float* lmi = gmi + Bb*Bb;

    mi_kernel<<<LOC_CTAS + GLB_CTAS, NT, smem>>>(lw2, lb2, lw3, lb3,
                                                 gw2, gb2, gw3, gb3,
                                                 lmi, gmi);
}

// round 11
// speedup vs baseline: 1.1495x; 1.0167x over previous
#include <cuda_runtime.h>

#define Bb 96
#define Tt 48
#define LD 64
#define GD 64
#define MT 10
#define HH 128

#define NT 256
#define SW_F 16384
#define SH1_STRIDE 129
#define SH1_F (Bb*SH1_STRIDE)
#define LOC_CTAS 576
#define GLB_CTAS 12

typedef unsigned long long ull;

__device__ float g_P[Bb*HH];      // sampled-locals @ gw1[:640] [96,128]
__device__ float g_Q[Bb*HH];      // globals @ gw1[640:] + gb1  [96,128]
__device__ float g_Bg[Bb*HH];     // globals @ lw1[64:] + lb1   [96,128]

__device__ __forceinline__ ull pack2(float lo, float hi){
    ull r; asm("mov.b64 %0, {%1, %2};" : "=l"(r) : "f"(lo), "f"(hi)); return r;
}
__device__ __forceinline__ void fma2(ull &d, ull a, ull b){
    asm("fma.rn.f32x2 %0, %1, %2, %0;" : "+l"(d) : "l"(a), "l"(b));
}
__device__ __forceinline__ float2 unpack2(ull v){
    float2 f; asm("mov.b64 {%0, %1}, %2;" : "=f"(f.x), "=f"(f.y) : "l"(v)); return f;
}

// ---------------------------------------------------------------------------
// Precompute Bg, Q, P per batch-row i (96 CTAs, ~5us).
// ---------------------------------------------------------------------------
__global__ __launch_bounds__(128) void precompute_pqb_kernel(
    const float* __restrict__ globals_, const float* __restrict__ locals_,
    const float* __restrict__ gw1, const float* __restrict__ gb1,
    const float* __restrict__ lw1, const float* __restrict__ lb1,
    const int* __restrict__ idx_t)
{
    __shared__ float lsrow[MT*LD];
    __shared__ float grow[GD];
    __shared__ int   sidx[MT];

    const int i = blockIdx.x;
    const int tid = threadIdx.x;

    if (tid < GD) grow[tid] = globals_[i*GD + tid];
    if (tid < MT) sidx[tid] = idx_t[i*MT + tid];
    __syncthreads();
    for (int idx = tid; idx < MT*LD; idx += 128) {
        int m = idx >> 6, k = idx & 63;
        lsrow[idx] = locals_[(i*Tt + sidx[m])*LD + k];
    }
    __syncthreads();

    const int h = tid;

    float bv = lb1[h];
    for (int k = 0; k < GD; k++) bv += grow[k] * lw1[(LD + k)*HH + h];
    g_Bg[i*HH + h] = bv;

    float qv = gb1[h];
    for (int k = 0; k < GD; k++) qv += grow[k] * gw1[(MT*LD + k)*HH + h];
    g_Q[i*HH + h] = qv;

    float pv = 0.f;
    for (int k = 0; k < MT*LD; k++) pv += lsrow[k] * gw1[k*HH + h];
    g_P[i*HH + h] = pv;
}

// ---------------------------------------------------------------------------
// Unified MI kernel. CTAs [0,576): locals path (computes its 8 A-rows in the
// prologue from locals_/lw1 — 8 | 48 so all 8 rows share batch index i).
// CTAs [576,588): globals path (loads its 8 P-rows from g_P).
// Then per row r: h1[j] = relu(arow8[r] + brows[j]); h2 = relu(h1@w2 + b2);
// out = h2.w3 + b3.  Geometry: 256 thr, 16 jg (6 j) x 16 hg (8 h), fp32.
// ---------------------------------------------------------------------------
__global__ void __launch_bounds__(NT, 1) mi_kernel(
    const float* __restrict__ locals_, const float* __restrict__ lw1,
    const float* __restrict__ lw2, const float* __restrict__ lb2,
    const float* __restrict__ lw3, const float* __restrict__ lb3,
    const float* __restrict__ gw2, const float* __restrict__ gb2,
    const float* __restrict__ gw3, const float* __restrict__ gb3,
    float* __restrict__ out_l, float* __restrict__ out_g)
{
    extern __shared__ float sm[];
    float* sw     = sm;                 // [128][128] w2, 64 KB
    float* sh1    = sm + SW_F;          // [96][129]  h1 tile (prologue: ltile alias)
    float* arow8  = sh1 + SH1_F;        // [8][128] this CTA's layer-1 left rows
    float* sw3    = arow8 + 8*HH;       // [128]

    const int bid = blockIdx.x;
    const bool isg = (bid >= LOC_CTAS);

    const float* w2 = isg ? gw2 : lw2;
    const float* b2 = isg ? gb2 : lb2;
    const float* w3 = isg ? gw3 : lw3;
    const float* b3 = isg ? gb3 : lb3;
    const float* brows = isg ? g_Q : g_Bg;
    float* out = isg ? out_g : out_l;
    const int row0 = (isg ? (bid - LOC_CTAS) : bid) * 8;

    const int tid = threadIdx.x;
    const int jg = tid >> 4;           // 0..15
    const int hg = tid & 15;           // 0..15
    const int hA = hg * 4;
    const int hB = 64 + hg * 4;
    const int jb = jg * 6;

    // ---- prologue: w2 -> smem, w3 -> smem ----
    const float4* w24 = (const float4*)w2;
    float4* sw4 = (float4*)sw;
    for (int idx = tid; idx < SW_F/4; idx += NT) sw4[idx] = w24[idx];
    if (tid < HH) sw3[tid] = w3[tid];

    if (isg) {
        // globals: stage 8 P rows
        for (int idx = tid; idx < 8*HH; idx += NT)
            arow8[idx] = g_P[row0*HH + idx];
        __syncthreads();
    } else {
        // locals: compute 8 A rows = locals[i, t0..t0+8) @ lw1[0:64]
        const int i  = bid / 6;
        const int t0 = (bid - i*6) * 8;
        float* ltile = sh1;            // reuse sh1 space as [8][64] temp
        for (int idx = tid; idx < 8*LD; idx += NT)
            ltile[idx] = locals_[(i*Tt + t0)*LD + idx];
        __syncthreads();

        const int h  = tid & 127;
        const int tg = tid >> 7;       // 0/1 -> t rows tg, tg+2, tg+4, tg+6
        float a0 = 0.f, a1 = 0.f, a2 = 0.f, a3 = 0.f;
        #pragma unroll 8
        for (int k = 0; k < LD; k++) {
            float w = lw1[k*HH + h];
            a0 += ltile[(tg  )*LD + k] * w;
            a1 += ltile[(tg+2)*LD + k] * w;
            a2 += ltile[(tg+4)*LD + k] * w;
            a3 += ltile[(tg+6)*LD + k] * w;
        }
        __syncthreads();               // ltile reads complete before any reuse of sh1
        arow8[(tg  )*HH + h] = a0;
        arow8[(tg+2)*HH + h] = a1;
        arow8[(tg+4)*HH + h] = a2;
        arow8[(tg+6)*HH + h] = a3;
        __syncthreads();               // arow8 ready for h1 builds
    }

    // b2 accumulator init (pairs), b3
    float2 q0 = *(const float2*)(b2 + hA);
    float2 q1 = *(const float2*)(b2 + hA + 2);
    float2 q2 = *(const float2*)(b2 + hB);
    float2 q3 = *(const float2*)(b2 + hB + 2);
    ull binit[4] = { pack2(q0.x,q0.y), pack2(q1.x,q1.y), pack2(q2.x,q2.y), pack2(q3.x,q3.y) };
    const float b3v = b3[0];

    const ull* swp = (const ull*)sw;   // w2 pairs: swp[k*64 + h/2]

    for (int r = 0; r < 8; r++) {
        const int row = row0 + r;
        const float* arow = arow8 + r*HH;

        __syncthreads();   // prior iter FFMA loop done reading sh1 (r=0: orders prologue)

        // h1[j][k] = relu(arow[k] + brows[j][k])
        for (int idx = tid; idx < Bb*HH; idx += NT) {
            int k = idx & 127;
            float v = arow[k] + brows[idx];
            sh1[(idx >> 7)*SH1_STRIDE + k] = v > 0.f ? v : 0.f;
        }
        __syncthreads();

        ull acc[6][4];
        #pragma unroll
        for (int jj = 0; jj < 6; jj++) {
            #pragma unroll
            for (int p = 0; p < 4; p++) acc[jj][p] = binit[p];
        }

        #pragma unroll 4
        for (int k = 0; k < HH; k++) {
            ull bf0 = swp[(k << 6) + hg*2];
            ull bf1 = swp[(k << 6) + hg*2 + 1];
            ull bf2 = swp[(k << 6) + 32 + hg*2];
            ull bf3 = swp[(k << 6) + 32 + hg*2 + 1];
            #pragma unroll
            for (int jj = 0; jj < 6; jj++) {
                float a = sh1[(jb + jj)*SH1_STRIDE + k];
                ull a2 = pack2(a, a);
                fma2(acc[jj][0], a2, bf0);
                fma2(acc[jj][1], a2, bf1);
                fma2(acc[jj][2], a2, bf2);
                fma2(acc[jj][3], a2, bf3);
            }
        }

        // Epilogue: relu(h2) . w3, reduce over 16 hg lanes
        #pragma unroll
        for (int jj = 0; jj < 6; jj++) {
            float2 v0 = unpack2(acc[jj][0]);
            float2 v1 = unpack2(acc[jj][1]);
            float2 v2 = unpack2(acc[jj][2]);
            float2 v3 = unpack2(acc[jj][3]);
            float s = fmaxf(v0.x,0.f)*sw3[hA]   + fmaxf(v0.y,0.f)*sw3[hA+1]
                    + fmaxf(v1.x,0.f)*sw3[hA+2] + fmaxf(v1.y,0.f)*sw3[hA+3]
                    + fmaxf(v2.x,0.f)*sw3[hB]   + fmaxf(v2.y,0.f)*sw3[hB+1]
                    + fmaxf(v3.x,0.f)*sw3[hB+2] + fmaxf(v3.y,0.f)*sw3[hB+3];
            s += __shfl_xor_sync(0xffffffffu, s, 1);
            s += __shfl_xor_sync(0xffffffffu, s, 2);
            s += __shfl_xor_sync(0xffffffffu, s, 4);
            s += __shfl_xor_sync(0xffffffffu, s, 8);
            if (hg == 0) {
                int j = jb + jj;
                int o;
                if (!isg) {
                    int ii = row / Tt, tt = row - ii*Tt;
                    o = tt*(Bb*Bb) + ii*Bb + j;      // locals_mi[t][i][j]
                } else {
                    o = row*Bb + j;                   // globals_mi[i][j]
                }
                out[o] = s + b3v;
            }
        }
    }
}

// ---------------------------------------------------------------------------
extern "C" void kernel_launch(void* const* d_in, const int* in_sizes, int n_in,
                              void* d_out, int out_size)
{
    const float* globals_ = (const float*)d_in[0];
    const float* locals_  = (const float*)d_in[1];
    const float* gw1 = (const float*)d_in[2];
    const float* gb1 = (const float*)d_in[3];
    const float* gw2 = (const float*)d_in[4];
    const float* gb2 = (const float*)d_in[5];
    const float* gw3 = (const float*)d_in[6];
    const float* gb3 = (const float*)d_in[7];
    const float* lw1 = (const float*)d_in[8];
    const float* lb1 = (const float*)d_in[9];
    const float* lw2 = (const float*)d_in[10];
    const float* lb2 = (const float*)d_in[11];
    const float* lw3 = (const float*)d_in[12];
    const float* lb3 = (const float*)d_in[13];
    const int*  idx_t = (const int*)d_in[14];

    float* out = (float*)d_out;

    // Pass-through outputs
    cudaMemcpyAsync(out, globals_, (size_t)Bb*GD*sizeof(float),
                    cudaMemcpyDeviceToDevice, 0);
    cudaMemcpyAsync(out + Bb*GD, locals_, (size_t)Bb*Tt*LD*sizeof(float),
                    cudaMemcpyDeviceToDevice, 0);

    precompute_pqb_kernel<<<Bb, 128>>>(globals_, locals_, gw1, gb1, lw1, lb1, idx_t);

    size_t smem = (size_t)(SW_F + SH1_F + 8*HH + HH) * sizeof(float);
    cudaFuncSetAttribute(mi_kernel, cudaFuncAttributeMaxDynamicSharedMemorySize, (int)smem);

    float* gmi = out + (Bb*GD + Bb*Tt*LD);
    float* lmi = gmi + Bb*Bb;

    mi_kernel<<<LOC_CTAS + GLB_CTAS, NT, smem>>>(locals_, lw1,
                                                 lw2, lb2, lw3, lb3,
                                                 gw2, gb2, gw3, gb3,
                                                 lmi, gmi);
}